// round 2
// baseline (speedup 1.0000x reference)
#include <cuda_runtime.h>
#include <cuda_bf16.h>

// ---------------------------------------------------------------------------
// Graph attention: Q/K/V projections + dst-segment softmax + scatter aggregate
// Strategy:
//   1. fused fp32 GEMM (f32x2 packed FMA) -> g_Q, g_K, g_V scratch
//   2. build dst-sorted CSR (hist + 2-level scan + scatter)
//   3. one warp per destination node: online softmax in registers
// ---------------------------------------------------------------------------

#define HID 128
#define MAXN 100352
#define MAXE 1700000

__device__ float g_Q[(size_t)MAXN * HID];
__device__ float g_K[(size_t)MAXN * HID];
__device__ float g_V[(size_t)MAXN * HID];
__device__ int   g_cnt[MAXN];
__device__ int   g_cursor[MAXN];
__device__ int   g_rowptr[MAXN + 1];
__device__ int   g_blksum[256];
__device__ int   g_ssrc[MAXE];

// ---- packed f32x2 helpers (PTX-only; ptxas never emits FFMA2 from C++) ----
__device__ __forceinline__ void fma2(unsigned long long& d,
                                     unsigned long long a,
                                     unsigned long long b) {
    asm volatile("fma.rn.f32x2 %0, %1, %2, %0;" : "+l"(d) : "l"(a), "l"(b));
}
__device__ __forceinline__ unsigned long long dup2(float x) {
    unsigned long long r;
    asm("mov.b64 %0, {%1, %1};" : "=l"(r) : "f"(x));
    return r;
}
__device__ __forceinline__ void unpk(unsigned long long v, float& lo, float& hi) {
    asm("mov.b64 {%0, %1}, %2;" : "=f"(lo), "=f"(hi) : "l"(v));
}

// ---------------------------------------------------------------------------
// Kernel 1: QKV projection GEMM.
// grid.y selects (Wq,bq)->g_Q / (Wk,bk)->g_K / (Wv,bv)->g_V.
// Block tile 64 rows x 128 cols, k-chunk 32. 256 threads.
// Thread (i = warp 0..7 -> 8 rows, j = lane 0..31 -> 4 cols).
// Accumulators: 16 x f32x2 (row-pairs packed), B scalar duplicated.
// ---------------------------------------------------------------------------
__global__ __launch_bounds__(256)
void qkv_gemm_kernel(const float* __restrict__ h,
                     const float* __restrict__ Wq, const float* __restrict__ bq,
                     const float* __restrict__ Wk, const float* __restrict__ bk,
                     const float* __restrict__ Wv, const float* __restrict__ bv,
                     int n) {
    const float* W;
    const float* bias;
    float* out;
    if (blockIdx.y == 0)      { W = Wq; bias = bq; out = g_Q; }
    else if (blockIdx.y == 1) { W = Wk; bias = bk; out = g_K; }
    else                      { W = Wv; bias = bv; out = g_V; }

    __shared__ __align__(16) float hs_t[32][66];   // [kk][row], padded
    __shared__ __align__(16) float ws[32][HID];    // [kk][col]

    const int tid  = threadIdx.x;
    const int i    = tid >> 5;      // warp id: rows 8i..8i+7
    const int j    = tid & 31;      // lane id: cols 4j..4j+3
    const int row0 = blockIdx.x * 64;

    unsigned long long acc[4][4];
#pragma unroll
    for (int a = 0; a < 4; a++)
#pragma unroll
        for (int b = 0; b < 4; b++) acc[a][b] = 0ull;

    for (int k0 = 0; k0 < HID; k0 += 32) {
        // load h tile transposed: hs_t[kk][r]
        for (int t = tid; t < 64 * 32; t += 256) {
            int r  = t >> 5;
            int kk = t & 31;
            int row = row0 + r;
            float v = (row < n) ? h[(size_t)row * HID + k0 + kk] : 0.0f;
            hs_t[kk][r] = v;
        }
        // load W chunk: ws[kk][c]
        for (int t = tid; t < 32 * HID; t += 256) {
            int kk = t >> 7;
            int c  = t & 127;
            ws[kk][c] = W[(size_t)(k0 + kk) * HID + c];
        }
        __syncthreads();

#pragma unroll
        for (int kk = 0; kk < 32; kk++) {
            const unsigned long long* ap =
                reinterpret_cast<const unsigned long long*>(&hs_t[kk][i * 8]);
            unsigned long long A0 = ap[0], A1 = ap[1], A2 = ap[2], A3 = ap[3];
            float4 b = *reinterpret_cast<const float4*>(&ws[kk][j * 4]);
            unsigned long long B0 = dup2(b.x), B1 = dup2(b.y),
                               B2 = dup2(b.z), B3 = dup2(b.w);
            fma2(acc[0][0], A0, B0); fma2(acc[0][1], A0, B1);
            fma2(acc[0][2], A0, B2); fma2(acc[0][3], A0, B3);
            fma2(acc[1][0], A1, B0); fma2(acc[1][1], A1, B1);
            fma2(acc[1][2], A1, B2); fma2(acc[1][3], A1, B3);
            fma2(acc[2][0], A2, B0); fma2(acc[2][1], A2, B1);
            fma2(acc[2][2], A2, B2); fma2(acc[2][3], A2, B3);
            fma2(acc[3][0], A3, B0); fma2(acc[3][1], A3, B1);
            fma2(acc[3][2], A3, B2); fma2(acc[3][3], A3, B3);
        }
        __syncthreads();
    }

    // epilogue: rows (8i+2rp, 8i+2rp+1), cols 4j..4j+3
    const float4 bb = *reinterpret_cast<const float4*>(&bias[j * 4]);
#pragma unroll
    for (int rp = 0; rp < 4; rp++) {
        float r0c0, r1c0, r0c1, r1c1, r0c2, r1c2, r0c3, r1c3;
        unpk(acc[rp][0], r0c0, r1c0);
        unpk(acc[rp][1], r0c1, r1c1);
        unpk(acc[rp][2], r0c2, r1c2);
        unpk(acc[rp][3], r0c3, r1c3);
        int row = row0 + i * 8 + rp * 2;
        if (row < n) {
            float2* p = reinterpret_cast<float2*>(&out[(size_t)row * HID + j * 4]);
            p[0] = make_float2(r0c0 + bb.x, r0c1 + bb.y);
            p[1] = make_float2(r0c2 + bb.z, r0c3 + bb.w);
        }
        if (row + 1 < n) {
            float2* p = reinterpret_cast<float2*>(&out[(size_t)(row + 1) * HID + j * 4]);
            p[0] = make_float2(r1c0 + bb.x, r1c1 + bb.y);
            p[1] = make_float2(r1c2 + bb.z, r1c3 + bb.w);
        }
    }
}

// ---------------------------------------------------------------------------
// CSR construction by destination
// ---------------------------------------------------------------------------
__global__ void zero_kernel(int n) {
    int gid = blockIdx.x * blockDim.x + threadIdx.x;
    if (gid < n) { g_cnt[gid] = 0; g_cursor[gid] = 0; }
}

__global__ void hist_kernel(const int* __restrict__ dst, int e) {
    int gid = blockIdx.x * blockDim.x + threadIdx.x;
    if (gid < e) atomicAdd(&g_cnt[dst[gid]], 1);
}

__global__ void scan_block_kernel(int n) {
    __shared__ int sm[1024];
    int tid = threadIdx.x;
    int gid = blockIdx.x * 1024 + tid;
    int v = (gid < n) ? g_cnt[gid] : 0;
    sm[tid] = v;
    __syncthreads();
    for (int off = 1; off < 1024; off <<= 1) {
        int t = (tid >= off) ? sm[tid - off] : 0;
        __syncthreads();
        sm[tid] += t;
        __syncthreads();
    }
    if (gid < n) g_rowptr[gid] = sm[tid] - v;  // exclusive within block
    if (tid == 1023) g_blksum[blockIdx.x] = sm[1023];
}

__global__ void scan_top_kernel(int nb) {
    if (threadIdx.x == 0) {
        int running = 0;
        for (int i = 0; i < nb; i++) {
            int t = g_blksum[i];
            g_blksum[i] = running;
            running += t;
        }
    }
}

__global__ void add_off_kernel(int n, int e) {
    int gid = blockIdx.x * blockDim.x + threadIdx.x;
    if (gid < n) g_rowptr[gid] += g_blksum[gid >> 10];
    if (gid == 0) g_rowptr[n] = e;
}

__global__ void scatter_kernel(const int* __restrict__ src,
                               const int* __restrict__ dst, int e) {
    int gid = blockIdx.x * blockDim.x + threadIdx.x;
    if (gid < e) {
        int d = dst[gid];
        int pos = g_rowptr[d] + atomicAdd(&g_cursor[d], 1);
        g_ssrc[pos] = src[gid];
    }
}

// ---------------------------------------------------------------------------
// Kernel 3: one warp per destination node, online softmax in registers.
// Lane l owns output cols [4l, 4l+4); head = l/4 spans lanes 4h..4h+3.
// ---------------------------------------------------------------------------
__global__ __launch_bounds__(256)
void attn_kernel(float* __restrict__ out, int n) {
    int gwarp = (blockIdx.x * blockDim.x + threadIdx.x) >> 5;
    if (gwarp >= n) return;
    int lane = threadIdx.x & 31;

    const float4* Q4 = reinterpret_cast<const float4*>(g_Q);
    const float4* K4 = reinterpret_cast<const float4*>(g_K);
    const float4* V4 = reinterpret_cast<const float4*>(g_V);

    float4 q = Q4[(size_t)gwarp * 32 + lane];
    int beg = g_rowptr[gwarp];
    int end = g_rowptr[gwarp + 1];

    float m = -__int_as_float(0x7f800000);  // -inf
    float s = 0.0f;
    float4 acc = make_float4(0.f, 0.f, 0.f, 0.f);

    for (int idx = beg; idx < end; idx++) {
        int sidx = __ldg(&g_ssrc[idx]);
        float4 k = K4[(size_t)sidx * 32 + lane];
        float sc = k.x * q.x + k.y * q.y + k.z * q.z + k.w * q.w;
        sc += __shfl_xor_sync(0xffffffffu, sc, 1);
        sc += __shfl_xor_sync(0xffffffffu, sc, 2);
        float mn = fmaxf(m, sc);
        float scale = __expf(m - mn);   // first iter: exp(-inf) = 0
        float p = __expf(sc - mn);
        float4 v = V4[(size_t)sidx * 32 + lane];
        s = s * scale + p;
        acc.x = acc.x * scale + p * v.x;
        acc.y = acc.y * scale + p * v.y;
        acc.z = acc.z * scale + p * v.z;
        acc.w = acc.w * scale + p * v.w;
        m = mn;
    }

    float4 o;
    if (end > beg) {
        float inv = 1.0f / s;
        o = make_float4(acc.x * inv, acc.y * inv, acc.z * inv, acc.w * inv);
    } else {
        o = make_float4(0.f, 0.f, 0.f, 0.f);  // empty segment -> zeros
    }
    reinterpret_cast<float4*>(out)[(size_t)gwarp * 32 + lane] = o;
}

// ---------------------------------------------------------------------------
extern "C" void kernel_launch(void* const* d_in, const int* in_sizes, int n_in,
                              void* d_out, int out_size) {
    const float* h   = (const float*)d_in[0];
    const int*   src = (const int*)d_in[1];
    const int*   dst = (const int*)d_in[2];
    const float* Wq  = (const float*)d_in[3];
    const float* bq  = (const float*)d_in[4];
    const float* Wk  = (const float*)d_in[5];
    const float* bk  = (const float*)d_in[6];
    const float* Wv  = (const float*)d_in[7];
    const float* bv  = (const float*)d_in[8];
    float* out = (float*)d_out;

    int n = in_sizes[0] / HID;
    int e = in_sizes[1];

    zero_kernel<<<(n + 255) / 256, 256>>>(n);
    qkv_gemm_kernel<<<dim3((n + 63) / 64, 3), 256>>>(h, Wq, bq, Wk, bk, Wv, bv, n);
    hist_kernel<<<(e + 255) / 256, 256>>>(dst, e);
    int nb = (n + 1023) / 1024;
    scan_block_kernel<<<nb, 1024>>>(n);
    scan_top_kernel<<<1, 32>>>(nb);
    add_off_kernel<<<(n + 255) / 256, 256>>>(n, e);
    scatter_kernel<<<(e + 255) / 256, 256>>>(src, dst, e);

    long long total_threads = (long long)n * 32;
    int attn_blocks = (int)((total_threads + 255) / 256);
    attn_kernel<<<attn_blocks, 256>>>(out, n);
}

// round 4
// speedup vs baseline: 1.2195x; 1.2195x over previous
#include <cuda_runtime.h>
#include <cuda_bf16.h>
#include <cstdint>

// ---------------------------------------------------------------------------
// Graph attention: QKV projections (mma.sync bf16 split GEMM on tensor pipe)
// + dst-sorted CSR + warp-per-node online softmax aggregate.
// tcgen05 unavailable (toolchain targets sm_103 without the 'a' feature set),
// so tensor work goes through arch-portable mma.sync/ldmatrix.
// ---------------------------------------------------------------------------

#define HID 128
#define MAXN 100352           // 784 * 128, >= N
#define MAXE 1700000

__device__ float g_Q[(size_t)MAXN * HID];
__device__ float g_K[(size_t)MAXN * HID];
__device__ float g_V[(size_t)MAXN * HID];
__device__ __nv_bfloat16 g_h_hi[(size_t)MAXN * HID];
__device__ __nv_bfloat16 g_h_lo[(size_t)MAXN * HID];
__device__ __nv_bfloat16 g_wt_hi[3 * HID * HID];  // [mat][n][k] = W[k][n]
__device__ __nv_bfloat16 g_wt_lo[3 * HID * HID];
__device__ int   g_cnt[MAXN];
__device__ int   g_cursor[MAXN];
__device__ int   g_rowptr[MAXN + 1];
__device__ int   g_blksum[256];
__device__ int   g_ssrc[MAXE];

// ---------------------------------------------------------------------------
__device__ __forceinline__ uint32_t smem_u32(const void* p) {
    uint32_t a;
    asm("{ .reg .u64 t; cvta.to.shared.u64 t, %1; cvt.u32.u64 %0, t; }"
        : "=r"(a) : "l"(p));
    return a;
}
__device__ __forceinline__ void ldsm_x4(uint32_t* d, uint32_t addr) {
    asm volatile("ldmatrix.sync.aligned.m8n8.x4.shared.b16 {%0,%1,%2,%3}, [%4];"
                 : "=r"(d[0]), "=r"(d[1]), "=r"(d[2]), "=r"(d[3]) : "r"(addr));
}
__device__ __forceinline__ void mma_bf16(float* c, const uint32_t* a,
                                         uint32_t b0, uint32_t b1) {
    asm volatile("mma.sync.aligned.m16n8k16.row.col.f32.bf16.bf16.f32 "
                 "{%0,%1,%2,%3}, {%4,%5,%6,%7}, {%8,%9}, {%0,%1,%2,%3};"
                 : "+f"(c[0]), "+f"(c[1]), "+f"(c[2]), "+f"(c[3])
                 : "r"(a[0]), "r"(a[1]), "r"(a[2]), "r"(a[3]),
                   "r"(b0), "r"(b1));
}

// smem tile layout: pitch 136 bf16 (272B = 17*16B -> conflict-free ldmatrix)
#define PITCH 136
#define TILE_BYTES (128 * PITCH * 2)            // 34816
#define OFF_AH 0
#define OFF_AL (OFF_AH + TILE_BYTES)
#define OFF_BH (OFF_AL + TILE_BYTES)
#define OFF_BL (OFF_BH + TILE_BYTES)
#define GEMM_SMEM (OFF_BL + TILE_BYTES)         // 139264

// ---------------------------------------------------------------------------
// Split h into bf16 hi/lo; zero-pad rows [n, MAXN).
// ---------------------------------------------------------------------------
__global__ __launch_bounds__(256)
void split_h_kernel(const float* __restrict__ h, int n_elems) {
    int gid = blockIdx.x * blockDim.x + threadIdx.x;
    size_t base = (size_t)gid * 4;
    if (base >= (size_t)MAXN * HID) return;
    float4 v;
    if (base + 3 < (size_t)n_elems) {
        v = *reinterpret_cast<const float4*>(h + base);
    } else {
        v.x = (base + 0 < (size_t)n_elems) ? h[base + 0] : 0.f;
        v.y = (base + 1 < (size_t)n_elems) ? h[base + 1] : 0.f;
        v.z = (base + 2 < (size_t)n_elems) ? h[base + 2] : 0.f;
        v.w = (base + 3 < (size_t)n_elems) ? h[base + 3] : 0.f;
    }
    __nv_bfloat16 hx = __float2bfloat16_rn(v.x);
    __nv_bfloat16 hy = __float2bfloat16_rn(v.y);
    __nv_bfloat16 hz = __float2bfloat16_rn(v.z);
    __nv_bfloat16 hw = __float2bfloat16_rn(v.w);
    __nv_bfloat16 lx = __float2bfloat16_rn(v.x - __bfloat162float(hx));
    __nv_bfloat16 ly = __float2bfloat16_rn(v.y - __bfloat162float(hy));
    __nv_bfloat16 lz = __float2bfloat16_rn(v.z - __bfloat162float(hz));
    __nv_bfloat16 lw = __float2bfloat16_rn(v.w - __bfloat162float(hw));
    __nv_bfloat162* ph = reinterpret_cast<__nv_bfloat162*>(g_h_hi + base);
    __nv_bfloat162* pl = reinterpret_cast<__nv_bfloat162*>(g_h_lo + base);
    ph[0] = __nv_bfloat162(hx, hy); ph[1] = __nv_bfloat162(hz, hw);
    pl[0] = __nv_bfloat162(lx, ly); pl[1] = __nv_bfloat162(lz, lw);
}

// ---------------------------------------------------------------------------
// Transpose + split W: Wt[mat][n][k] = W_mat[k][n]
// ---------------------------------------------------------------------------
__global__ __launch_bounds__(256)
void prep_w_kernel(const float* __restrict__ Wq, const float* __restrict__ Wk,
                   const float* __restrict__ Wv) {
    int gid = blockIdx.x * blockDim.x + threadIdx.x;
    if (gid >= 3 * HID * HID) return;
    int mat = gid >> 14;
    int nn  = (gid >> 7) & 127;
    int k   = gid & 127;
    const float* W = (mat == 0) ? Wq : (mat == 1) ? Wk : Wv;
    float x = W[k * HID + nn];
    __nv_bfloat16 hi = __float2bfloat16_rn(x);
    __nv_bfloat16 lo = __float2bfloat16_rn(x - __bfloat162float(hi));
    g_wt_hi[gid] = hi;
    g_wt_lo[gid] = lo;
}

// ---------------------------------------------------------------------------
// mma.sync GEMM: block = 128 rows x 128 cols x K=128; loops mats Q,K,V with
// A (h tile) resident in smem. D = Ah@Bh^T + Ah@Bl^T + Al@Bh^T.
// 8 warps: warp (wm = wid&3 -> 32 rows, wn = wid>>2 -> 64 cols).
// ---------------------------------------------------------------------------
__global__ __launch_bounds__(256)
void qkv_gemm_mma(const float* __restrict__ bq, const float* __restrict__ bk,
                  const float* __restrict__ bv) {
    extern __shared__ __align__(16) char smem[];
    const uint32_t sb = smem_u32(smem);
    const int tid  = threadIdx.x;
    const int wid  = tid >> 5;
    const int lane = tid & 31;
    const int wm   = wid & 3;
    const int wn   = wid >> 2;
    const int row0 = blockIdx.x * 128;

    // Stage A hi/lo: 128 rows x 128 bf16, pitch 136
    {
        const uint4* srcH = reinterpret_cast<const uint4*>(g_h_hi + (size_t)row0 * HID);
        const uint4* srcL = reinterpret_cast<const uint4*>(g_h_lo + (size_t)row0 * HID);
        for (int t = tid; t < 2048; t += 256) {
            int r = t >> 4;
            int c = t & 15;
            uint32_t doff = (uint32_t)(r * (PITCH * 2) + c * 16);
            *reinterpret_cast<uint4*>(smem + OFF_AH + doff) = srcH[t];
            *reinterpret_cast<uint4*>(smem + OFF_AL + doff) = srcL[t];
        }
    }

    // ldmatrix address precompute
    const int a_lrow = lane & 15;
    const int a_lsel = lane >> 4;
    const int b_lrow = (lane & 7) + ((lane >> 4) & 1) * 8;
    const int b_lk   = ((lane >> 3) & 1) * 8;

    for (int mat = 0; mat < 3; mat++) {
        float* out;
        const float* bias;
        if (mat == 0)      { out = g_Q; bias = bq; }
        else if (mat == 1) { out = g_K; bias = bk; }
        else               { out = g_V; bias = bv; }

        __syncthreads();   // prior compute done reading B (and A staged, iter 0)
        {
            const uint4* srcH = reinterpret_cast<const uint4*>(g_wt_hi + (size_t)mat * HID * HID);
            const uint4* srcL = reinterpret_cast<const uint4*>(g_wt_lo + (size_t)mat * HID * HID);
            for (int t = tid; t < 2048; t += 256) {
                int r = t >> 4;
                int c = t & 15;
                uint32_t doff = (uint32_t)(r * (PITCH * 2) + c * 16);
                *reinterpret_cast<uint4*>(smem + OFF_BH + doff) = srcH[t];
                *reinterpret_cast<uint4*>(smem + OFF_BL + doff) = srcL[t];
            }
        }
        __syncthreads();

        float acc[2][8][4];
#pragma unroll
        for (int mi = 0; mi < 2; mi++)
#pragma unroll
            for (int ni = 0; ni < 8; ni++)
#pragma unroll
                for (int r = 0; r < 4; r++) acc[mi][ni][r] = 0.f;

#pragma unroll
        for (int ks = 0; ks < 8; ks++) {
            uint32_t aH[2][4], aL[2][4], bH[4][4], bL[4][4];
#pragma unroll
            for (int mi = 0; mi < 2; mi++) {
                uint32_t off = (uint32_t)(((wm * 32 + mi * 16 + a_lrow) * PITCH +
                                           ks * 16 + a_lsel * 8) * 2);
                ldsm_x4(aH[mi], sb + OFF_AH + off);
                ldsm_x4(aL[mi], sb + OFF_AL + off);
            }
#pragma unroll
            for (int np = 0; np < 4; np++) {
                uint32_t off = (uint32_t)(((wn * 64 + np * 16 + b_lrow) * PITCH +
                                           ks * 16 + b_lk) * 2);
                ldsm_x4(bH[np], sb + OFF_BH + off);
                ldsm_x4(bL[np], sb + OFF_BL + off);
            }
#pragma unroll
            for (int mi = 0; mi < 2; mi++)
#pragma unroll
                for (int ni = 0; ni < 8; ni++) {
                    int np = ni >> 1, rb = (ni & 1) * 2;
                    mma_bf16(acc[mi][ni], aH[mi], bH[np][rb], bH[np][rb + 1]);
                    mma_bf16(acc[mi][ni], aH[mi], bL[np][rb], bL[np][rb + 1]);
                    mma_bf16(acc[mi][ni], aL[mi], bH[np][rb], bH[np][rb + 1]);
                }
        }

        // Epilogue: c-frag (row = l/4 [+8], col = (l%4)*2 [+1])
#pragma unroll
        for (int mi = 0; mi < 2; mi++) {
            int row = row0 + wm * 32 + mi * 16 + (lane >> 2);
#pragma unroll
            for (int ni = 0; ni < 8; ni++) {
                int col = wn * 64 + ni * 8 + (lane & 3) * 2;
                float bx = __ldg(&bias[col]);
                float by = __ldg(&bias[col + 1]);
                *reinterpret_cast<float2*>(&out[(size_t)row * HID + col]) =
                    make_float2(acc[mi][ni][0] + bx, acc[mi][ni][1] + by);
                *reinterpret_cast<float2*>(&out[(size_t)(row + 8) * HID + col]) =
                    make_float2(acc[mi][ni][2] + bx, acc[mi][ni][3] + by);
            }
        }
    }
}

// ---------------------------------------------------------------------------
// CSR construction by destination
// ---------------------------------------------------------------------------
__global__ void zero_kernel(int n) {
    int gid = blockIdx.x * blockDim.x + threadIdx.x;
    if (gid < n) { g_cnt[gid] = 0; g_cursor[gid] = 0; }
}

__global__ void hist_kernel(const int* __restrict__ dst, int e) {
    int gid = blockIdx.x * blockDim.x + threadIdx.x;
    if (gid < e) atomicAdd(&g_cnt[dst[gid]], 1);
}

__global__ void scan_block_kernel(int n) {
    __shared__ int sm[1024];
    int tid = threadIdx.x;
    int gid = blockIdx.x * 1024 + tid;
    int v = (gid < n) ? g_cnt[gid] : 0;
    sm[tid] = v;
    __syncthreads();
    for (int off = 1; off < 1024; off <<= 1) {
        int t = (tid >= off) ? sm[tid - off] : 0;
        __syncthreads();
        sm[tid] += t;
        __syncthreads();
    }
    if (gid < n) g_rowptr[gid] = sm[tid] - v;  // exclusive within block
    if (tid == 1023) g_blksum[blockIdx.x] = sm[1023];
}

__global__ void scan_top_kernel(int nb) {
    if (threadIdx.x == 0) {
        int running = 0;
        for (int i = 0; i < nb; i++) {
            int t = g_blksum[i];
            g_blksum[i] = running;
            running += t;
        }
    }
}

__global__ void add_off_kernel(int n, int e) {
    int gid = blockIdx.x * blockDim.x + threadIdx.x;
    if (gid < n) g_rowptr[gid] += g_blksum[gid >> 10];
    if (gid == 0) g_rowptr[n] = e;
}

__global__ void scatter_kernel(const int* __restrict__ src,
                               const int* __restrict__ dst, int e) {
    int gid = blockIdx.x * blockDim.x + threadIdx.x;
    if (gid < e) {
        int d = dst[gid];
        int pos = g_rowptr[d] + atomicAdd(&g_cursor[d], 1);
        g_ssrc[pos] = src[gid];
    }
}

// ---------------------------------------------------------------------------
// One warp per destination node, online softmax in registers.
// ---------------------------------------------------------------------------
__global__ __launch_bounds__(256)
void attn_kernel(float* __restrict__ out, int n) {
    int gwarp = (blockIdx.x * blockDim.x + threadIdx.x) >> 5;
    if (gwarp >= n) return;
    int lane = threadIdx.x & 31;

    const float4* Q4 = reinterpret_cast<const float4*>(g_Q);
    const float4* K4 = reinterpret_cast<const float4*>(g_K);
    const float4* V4 = reinterpret_cast<const float4*>(g_V);

    float4 q = Q4[(size_t)gwarp * 32 + lane];
    int beg = g_rowptr[gwarp];
    int end = g_rowptr[gwarp + 1];

    float m = -__int_as_float(0x7f800000);  // -inf
    float s = 0.0f;
    float4 acc = make_float4(0.f, 0.f, 0.f, 0.f);

    for (int idx = beg; idx < end; idx++) {
        int sidx = __ldg(&g_ssrc[idx]);
        float4 k = K4[(size_t)sidx * 32 + lane];
        float sc = k.x * q.x + k.y * q.y + k.z * q.z + k.w * q.w;
        sc += __shfl_xor_sync(0xffffffffu, sc, 1);
        sc += __shfl_xor_sync(0xffffffffu, sc, 2);
        float mn = fmaxf(m, sc);
        float scale = __expf(m - mn);   // first iter: exp(-inf) = 0
        float p = __expf(sc - mn);
        float4 v = V4[(size_t)sidx * 32 + lane];
        s = s * scale + p;
        acc.x = acc.x * scale + p * v.x;
        acc.y = acc.y * scale + p * v.y;
        acc.z = acc.z * scale + p * v.z;
        acc.w = acc.w * scale + p * v.w;
        m = mn;
    }

    float4 o;
    if (end > beg) {
        float inv = 1.0f / s;
        o = make_float4(acc.x * inv, acc.y * inv, acc.z * inv, acc.w * inv);
    } else {
        o = make_float4(0.f, 0.f, 0.f, 0.f);
    }
    reinterpret_cast<float4*>(out)[(size_t)gwarp * 32 + lane] = o;
}

// ---------------------------------------------------------------------------
extern "C" void kernel_launch(void* const* d_in, const int* in_sizes, int n_in,
                              void* d_out, int out_size) {
    const float* h   = (const float*)d_in[0];
    const int*   src = (const int*)d_in[1];
    const int*   dst = (const int*)d_in[2];
    const float* Wq  = (const float*)d_in[3];
    const float* bq  = (const float*)d_in[4];
    const float* Wk  = (const float*)d_in[5];
    const float* bk  = (const float*)d_in[6];
    const float* Wv  = (const float*)d_in[7];
    const float* bv  = (const float*)d_in[8];
    float* out = (float*)d_out;

    int n = in_sizes[0] / HID;
    int e = in_sizes[1];

    cudaFuncSetAttribute(qkv_gemm_mma,
                         cudaFuncAttributeMaxDynamicSharedMemorySize, GEMM_SMEM);

    zero_kernel<<<(n + 255) / 256, 256>>>(n);
    split_h_kernel<<<(MAXN * HID / 4 + 255) / 256, 256>>>(h, n * HID);
    prep_w_kernel<<<(3 * HID * HID + 255) / 256, 256>>>(Wq, Wk, Wv);

    int mblocks = (n + 127) / 128;
    qkv_gemm_mma<<<mblocks, 256, GEMM_SMEM>>>(bq, bk, bv);

    hist_kernel<<<(e + 255) / 256, 256>>>(dst, e);
    int nb = (n + 1023) / 1024;
    scan_block_kernel<<<nb, 1024>>>(n);
    scan_top_kernel<<<1, 32>>>(nb);
    add_off_kernel<<<(n + 255) / 256, 256>>>(n, e);
    scatter_kernel<<<(e + 255) / 256, 256>>>(src, dst, e);

    long long total_threads = (long long)n * 32;
    int attn_blocks = (int)((total_threads + 255) / 256);
    attn_kernel<<<attn_blocks, 256>>>(out, n);
}

// round 5
// speedup vs baseline: 1.2341x; 1.0119x over previous
#include <cuda_runtime.h>
#include <cuda_bf16.h>
#include <cstdint>

// ---------------------------------------------------------------------------
// Graph attention: QKV projections (mma.sync bf16 split GEMM, fused fp32->bf16
// split in A staging, 2 CTAs/SM) + dst-sorted CSR + warp-per-node softmax.
// ---------------------------------------------------------------------------

#define HID 128
#define MAXN 100352           // 784 * 128, >= N
#define MAXE 1700000

__device__ float g_Q[(size_t)MAXN * HID];
__device__ float g_K[(size_t)MAXN * HID];
__device__ float g_V[(size_t)MAXN * HID];
__device__ __nv_bfloat16 g_wt_hi[3 * HID * HID];  // [mat][n][k] = W[k][n]
__device__ __nv_bfloat16 g_wt_lo[3 * HID * HID];
__device__ int   g_cnt[MAXN];
__device__ int   g_cursor[MAXN];
__device__ int   g_rowptr[MAXN + 1];
__device__ int   g_blksum[256];
__device__ int   g_ssrc[MAXE];

// ---------------------------------------------------------------------------
__device__ __forceinline__ uint32_t smem_u32(const void* p) {
    uint32_t a;
    asm("{ .reg .u64 t; cvta.to.shared.u64 t, %1; cvt.u32.u64 %0, t; }"
        : "=r"(a) : "l"(p));
    return a;
}
__device__ __forceinline__ void ldsm_x4(uint32_t* d, uint32_t addr) {
    asm volatile("ldmatrix.sync.aligned.m8n8.x4.shared.b16 {%0,%1,%2,%3}, [%4];"
                 : "=r"(d[0]), "=r"(d[1]), "=r"(d[2]), "=r"(d[3]) : "r"(addr));
}
__device__ __forceinline__ void mma_bf16(float* c, const uint32_t* a,
                                         uint32_t b0, uint32_t b1) {
    asm volatile("mma.sync.aligned.m16n8k16.row.col.f32.bf16.bf16.f32 "
                 "{%0,%1,%2,%3}, {%4,%5,%6,%7}, {%8,%9}, {%0,%1,%2,%3};"
                 : "+f"(c[0]), "+f"(c[1]), "+f"(c[2]), "+f"(c[3])
                 : "r"(a[0]), "r"(a[1]), "r"(a[2]), "r"(a[3]),
                   "r"(b0), "r"(b1));
}
__device__ __forceinline__ uint32_t bf2_bits(float x, float y) {
    __nv_bfloat162 t(__float2bfloat16_rn(x), __float2bfloat16_rn(y));
    return *reinterpret_cast<uint32_t*>(&t);
}

// smem tile layout: pitch 136 bf16 (272B = 17*16B -> conflict-free ldmatrix)
#define PITCH 136
#define A_TILE_BYTES (64 * PITCH * 2)            // 17408
#define B_TILE_BYTES (128 * PITCH * 2)           // 34816
#define OFF_AH 0
#define OFF_AL (OFF_AH + A_TILE_BYTES)
#define OFF_BH (OFF_AL + A_TILE_BYTES)
#define OFF_BL (OFF_BH + B_TILE_BYTES)
#define GEMM_SMEM (OFF_BL + B_TILE_BYTES)        // 104448 -> 2 CTAs/SM

// ---------------------------------------------------------------------------
// Transpose + split W: Wt[mat][n][k] = W_mat[k][n]
// ---------------------------------------------------------------------------
__global__ __launch_bounds__(256)
void prep_w_kernel(const float* __restrict__ Wq, const float* __restrict__ Wk,
                   const float* __restrict__ Wv) {
    int gid = blockIdx.x * blockDim.x + threadIdx.x;
    if (gid >= 3 * HID * HID) return;
    int mat = gid >> 14;
    int nn  = (gid >> 7) & 127;
    int k   = gid & 127;
    const float* W = (mat == 0) ? Wq : (mat == 1) ? Wk : Wv;
    float x = W[k * HID + nn];
    __nv_bfloat16 hi = __float2bfloat16_rn(x);
    __nv_bfloat16 lo = __float2bfloat16_rn(x - __bfloat162float(hi));
    g_wt_hi[gid] = hi;
    g_wt_lo[gid] = lo;
}

// ---------------------------------------------------------------------------
// mma.sync GEMM: block = 64 rows x 128 cols x K=128; loops mats Q,K,V with
// A (h tile, converted fp32->bf16 hi/lo in staging) resident in smem.
// D = Ah@Bh^T + Ah@Bl^T + Al@Bh^T.
// 8 warps: wm = wid&1 -> 32 rows, wn = wid>>1 -> 32 cols (warp tile 32x32).
// ---------------------------------------------------------------------------
__global__ __launch_bounds__(256, 2)
void qkv_gemm_mma(const float* __restrict__ h,
                  const float* __restrict__ bq, const float* __restrict__ bk,
                  const float* __restrict__ bv, int n) {
    extern __shared__ __align__(16) char smem[];
    const uint32_t sb = smem_u32(smem);
    const int tid  = threadIdx.x;
    const int wid  = tid >> 5;
    const int lane = tid & 31;
    const int wm   = wid & 1;
    const int wn   = wid >> 1;
    const int row0 = blockIdx.x * 64;

    // Stage A: load fp32 h rows, split to bf16 hi/lo, store pitch-136.
    // 64 rows x 32 float4-chunks; 8 iters per thread.
    for (int t = tid; t < 2048; t += 256) {
        int r = t >> 5;
        int c = t & 31;                       // float4 index within row
        int row = row0 + r;
        float4 v = make_float4(0.f, 0.f, 0.f, 0.f);
        if (row < n)
            v = *reinterpret_cast<const float4*>(h + (size_t)row * HID + c * 4);
        float hx = __bfloat162float(__float2bfloat16_rn(v.x));
        float hy = __bfloat162float(__float2bfloat16_rn(v.y));
        float hz = __bfloat162float(__float2bfloat16_rn(v.z));
        float hw = __bfloat162float(__float2bfloat16_rn(v.w));
        uint2 phi, plo;
        phi.x = bf2_bits(v.x, v.y);
        phi.y = bf2_bits(v.z, v.w);
        plo.x = bf2_bits(v.x - hx, v.y - hy);
        plo.y = bf2_bits(v.z - hz, v.w - hw);
        uint32_t doff = (uint32_t)(r * (PITCH * 2) + c * 8);
        *reinterpret_cast<uint2*>(smem + OFF_AH + doff) = phi;
        *reinterpret_cast<uint2*>(smem + OFF_AL + doff) = plo;
    }

    // ldmatrix address precompute
    const int a_lrow = lane & 15;
    const int a_lsel = lane >> 4;
    const int b_lrow = (lane & 7) + ((lane >> 4) & 1) * 8;
    const int b_lk   = ((lane >> 3) & 1) * 8;

    for (int mat = 0; mat < 3; mat++) {
        float* out;
        const float* bias;
        if (mat == 0)      { out = g_Q; bias = bq; }
        else if (mat == 1) { out = g_K; bias = bk; }
        else               { out = g_V; bias = bv; }

        __syncthreads();   // prior compute done reading B (and A staged, iter 0)
        {
            const uint4* srcH = reinterpret_cast<const uint4*>(g_wt_hi + (size_t)mat * HID * HID);
            const uint4* srcL = reinterpret_cast<const uint4*>(g_wt_lo + (size_t)mat * HID * HID);
            for (int t = tid; t < 2048; t += 256) {
                int r = t >> 4;
                int c = t & 15;
                uint32_t doff = (uint32_t)(r * (PITCH * 2) + c * 16);
                *reinterpret_cast<uint4*>(smem + OFF_BH + doff) = srcH[t];
                *reinterpret_cast<uint4*>(smem + OFF_BL + doff) = srcL[t];
            }
        }
        __syncthreads();

        float acc[2][4][4];
#pragma unroll
        for (int mi = 0; mi < 2; mi++)
#pragma unroll
            for (int ni = 0; ni < 4; ni++)
#pragma unroll
                for (int r = 0; r < 4; r++) acc[mi][ni][r] = 0.f;

#pragma unroll
        for (int ks = 0; ks < 8; ks++) {
            uint32_t aH[2][4], aL[2][4], bH[2][4], bL[2][4];
#pragma unroll
            for (int mi = 0; mi < 2; mi++) {
                uint32_t off = (uint32_t)(((wm * 32 + mi * 16 + a_lrow) * PITCH +
                                           ks * 16 + a_lsel * 8) * 2);
                ldsm_x4(aH[mi], sb + OFF_AH + off);
                ldsm_x4(aL[mi], sb + OFF_AL + off);
            }
#pragma unroll
            for (int np = 0; np < 2; np++) {
                uint32_t off = (uint32_t)(((wn * 32 + np * 16 + b_lrow) * PITCH +
                                           ks * 16 + b_lk) * 2);
                ldsm_x4(bH[np], sb + OFF_BH + off);
                ldsm_x4(bL[np], sb + OFF_BL + off);
            }
#pragma unroll
            for (int mi = 0; mi < 2; mi++)
#pragma unroll
                for (int ni = 0; ni < 4; ni++) {
                    int np = ni >> 1, rb = (ni & 1) * 2;
                    mma_bf16(acc[mi][ni], aH[mi], bH[np][rb], bH[np][rb + 1]);
                    mma_bf16(acc[mi][ni], aH[mi], bL[np][rb], bL[np][rb + 1]);
                    mma_bf16(acc[mi][ni], aL[mi], bH[np][rb], bH[np][rb + 1]);
                }
        }

        // Epilogue: c-frag (row = l/4 [+8], col = (l%4)*2 [+1])
#pragma unroll
        for (int mi = 0; mi < 2; mi++) {
            int row = row0 + wm * 32 + mi * 16 + (lane >> 2);
#pragma unroll
            for (int ni = 0; ni < 4; ni++) {
                int col = wn * 32 + ni * 8 + (lane & 3) * 2;
                float bx = __ldg(&bias[col]);
                float by = __ldg(&bias[col + 1]);
                *reinterpret_cast<float2*>(&out[(size_t)row * HID + col]) =
                    make_float2(acc[mi][ni][0] + bx, acc[mi][ni][1] + by);
                *reinterpret_cast<float2*>(&out[(size_t)(row + 8) * HID + col]) =
                    make_float2(acc[mi][ni][2] + bx, acc[mi][ni][3] + by);
            }
        }
    }
}

// ---------------------------------------------------------------------------
// CSR construction by destination
// ---------------------------------------------------------------------------
__global__ void zero_kernel(int n) {
    int gid = blockIdx.x * blockDim.x + threadIdx.x;
    if (gid < n) { g_cnt[gid] = 0; g_cursor[gid] = 0; }
}

__global__ void hist_kernel(const int* __restrict__ dst, int e) {
    int gid = blockIdx.x * blockDim.x + threadIdx.x;
    if (gid < e) atomicAdd(&g_cnt[dst[gid]], 1);
}

__global__ void scan_block_kernel(int n) {
    __shared__ int sm[1024];
    int tid = threadIdx.x;
    int gid = blockIdx.x * 1024 + tid;
    int v = (gid < n) ? g_cnt[gid] : 0;
    sm[tid] = v;
    __syncthreads();
    for (int off = 1; off < 1024; off <<= 1) {
        int t = (tid >= off) ? sm[tid - off] : 0;
        __syncthreads();
        sm[tid] += t;
        __syncthreads();
    }
    if (gid < n) g_rowptr[gid] = sm[tid] - v;  // exclusive within block
    if (tid == 1023) g_blksum[blockIdx.x] = sm[1023];
}

__global__ void scan_top_kernel(int nb) {
    if (threadIdx.x == 0) {
        int running = 0;
        for (int i = 0; i < nb; i++) {
            int t = g_blksum[i];
            g_blksum[i] = running;
            running += t;
        }
    }
}

__global__ void add_off_kernel(int n, int e) {
    int gid = blockIdx.x * blockDim.x + threadIdx.x;
    if (gid < n) g_rowptr[gid] += g_blksum[gid >> 10];
    if (gid == 0) g_rowptr[n] = e;
}

__global__ void scatter_kernel(const int* __restrict__ src,
                               const int* __restrict__ dst, int e) {
    int gid = blockIdx.x * blockDim.x + threadIdx.x;
    if (gid < e) {
        int d = dst[gid];
        int pos = g_rowptr[d] + atomicAdd(&g_cursor[d], 1);
        g_ssrc[pos] = src[gid];
    }
}

// ---------------------------------------------------------------------------
// One warp per destination node, online softmax in registers.
// ---------------------------------------------------------------------------
__global__ __launch_bounds__(256)
void attn_kernel(float* __restrict__ out, int n) {
    int gwarp = (blockIdx.x * blockDim.x + threadIdx.x) >> 5;
    if (gwarp >= n) return;
    int lane = threadIdx.x & 31;

    const float4* Q4 = reinterpret_cast<const float4*>(g_Q);
    const float4* K4 = reinterpret_cast<const float4*>(g_K);
    const float4* V4 = reinterpret_cast<const float4*>(g_V);

    float4 q = Q4[(size_t)gwarp * 32 + lane];
    int beg = g_rowptr[gwarp];
    int end = g_rowptr[gwarp + 1];

    float m = -__int_as_float(0x7f800000);  // -inf
    float s = 0.0f;
    float4 acc = make_float4(0.f, 0.f, 0.f, 0.f);

    for (int idx = beg; idx < end; idx++) {
        int sidx = __ldg(&g_ssrc[idx]);
        float4 k = K4[(size_t)sidx * 32 + lane];
        float sc = k.x * q.x + k.y * q.y + k.z * q.z + k.w * q.w;
        sc += __shfl_xor_sync(0xffffffffu, sc, 1);
        sc += __shfl_xor_sync(0xffffffffu, sc, 2);
        float mn = fmaxf(m, sc);
        float scale = __expf(m - mn);   // first iter: exp(-inf) = 0
        float p = __expf(sc - mn);
        float4 v = V4[(size_t)sidx * 32 + lane];
        s = s * scale + p;
        acc.x = acc.x * scale + p * v.x;
        acc.y = acc.y * scale + p * v.y;
        acc.z = acc.z * scale + p * v.z;
        acc.w = acc.w * scale + p * v.w;
        m = mn;
    }

    float4 o;
    if (end > beg) {
        float inv = 1.0f / s;
        o = make_float4(acc.x * inv, acc.y * inv, acc.z * inv, acc.w * inv);
    } else {
        o = make_float4(0.f, 0.f, 0.f, 0.f);
    }
    reinterpret_cast<float4*>(out)[(size_t)gwarp * 32 + lane] = o;
}

// ---------------------------------------------------------------------------
extern "C" void kernel_launch(void* const* d_in, const int* in_sizes, int n_in,
                              void* d_out, int out_size) {
    const float* h   = (const float*)d_in[0];
    const int*   src = (const int*)d_in[1];
    const int*   dst = (const int*)d_in[2];
    const float* Wq  = (const float*)d_in[3];
    const float* bq  = (const float*)d_in[4];
    const float* Wk  = (const float*)d_in[5];
    const float* bk  = (const float*)d_in[6];
    const float* Wv  = (const float*)d_in[7];
    const float* bv  = (const float*)d_in[8];
    float* out = (float*)d_out;

    int n = in_sizes[0] / HID;
    int e = in_sizes[1];

    cudaFuncSetAttribute(qkv_gemm_mma,
                         cudaFuncAttributeMaxDynamicSharedMemorySize, GEMM_SMEM);

    zero_kernel<<<(n + 255) / 256, 256>>>(n);
    prep_w_kernel<<<(3 * HID * HID + 255) / 256, 256>>>(Wq, Wk, Wv);

    int mblocks = (n + 63) / 64;
    qkv_gemm_mma<<<mblocks, 256, GEMM_SMEM>>>(h, bq, bk, bv, n);

    hist_kernel<<<(e + 255) / 256, 256>>>(dst, e);
    int nb = (n + 1023) / 1024;
    scan_block_kernel<<<nb, 1024>>>(n);
    scan_top_kernel<<<1, 32>>>(nb);
    add_off_kernel<<<(n + 255) / 256, 256>>>(n, e);
    scatter_kernel<<<(e + 255) / 256, 256>>>(src, dst, e);

    long long total_threads = (long long)n * 32;
    int attn_blocks = (int)((total_threads + 255) / 256);
    attn_kernel<<<attn_blocks, 256>>>(out, n);
}

// round 6
// speedup vs baseline: 1.2459x; 1.0095x over previous
#include <cuda_runtime.h>
#include <cuda_bf16.h>
#include <cstdint>

// ---------------------------------------------------------------------------
// Graph attention: QKV projections (mma.sync bf16 split GEMM, cp.async
// double-buffered B, fused fp32->bf16 split A staging) + dst-sorted CSR
// (built concurrently in a forked stream) + warp-per-node online softmax.
// ---------------------------------------------------------------------------

#define HID 128
#define MAXN 100352           // 784 * 128, >= N
#define MAXE 1700000

__device__ float g_Q[(size_t)MAXN * HID];
__device__ float g_K[(size_t)MAXN * HID];
__device__ float g_V[(size_t)MAXN * HID];
__device__ __nv_bfloat16 g_wt_hi[3 * HID * HID];  // [mat][n][k] = W[k][n]
__device__ __nv_bfloat16 g_wt_lo[3 * HID * HID];
__device__ int   g_cnt[MAXN];
__device__ int   g_cursor[MAXN];
__device__ int   g_rowptr[MAXN + 1];
__device__ int   g_blksum[256];
__device__ int   g_ssrc[MAXE];

// ---------------------------------------------------------------------------
__device__ __forceinline__ uint32_t smem_u32(const void* p) {
    uint32_t a;
    asm("{ .reg .u64 t; cvta.to.shared.u64 t, %1; cvt.u32.u64 %0, t; }"
        : "=r"(a) : "l"(p));
    return a;
}
__device__ __forceinline__ void ldsm_x4(uint32_t* d, uint32_t addr) {
    asm volatile("ldmatrix.sync.aligned.m8n8.x4.shared.b16 {%0,%1,%2,%3}, [%4];"
                 : "=r"(d[0]), "=r"(d[1]), "=r"(d[2]), "=r"(d[3]) : "r"(addr));
}
__device__ __forceinline__ void mma_bf16(float* c, const uint32_t* a,
                                         uint32_t b0, uint32_t b1) {
    asm volatile("mma.sync.aligned.m16n8k16.row.col.f32.bf16.bf16.f32 "
                 "{%0,%1,%2,%3}, {%4,%5,%6,%7}, {%8,%9}, {%0,%1,%2,%3};"
                 : "+f"(c[0]), "+f"(c[1]), "+f"(c[2]), "+f"(c[3])
                 : "r"(a[0]), "r"(a[1]), "r"(a[2]), "r"(a[3]),
                   "r"(b0), "r"(b1));
}
__device__ __forceinline__ uint32_t bf2_bits(float x, float y) {
    __nv_bfloat162 t(__float2bfloat16_rn(x), __float2bfloat16_rn(y));
    return *reinterpret_cast<uint32_t*>(&t);
}
__device__ __forceinline__ void cp16(uint32_t smem_dst, const void* gsrc) {
    asm volatile("cp.async.cg.shared.global [%0], [%1], 16;"
                 :: "r"(smem_dst), "l"(gsrc));
}
#define CP_COMMIT() asm volatile("cp.async.commit_group;" ::: "memory")
#define CP_WAIT(N)  asm volatile("cp.async.wait_group %0;" :: "n"(N) : "memory")

// smem tile layout: pitch 136 bf16 (272B = 17*16B -> conflict-free ldmatrix)
#define PITCH 136
#define TILE_BYTES (128 * PITCH * 2)             // 34816
#define OFF_AH 0
#define OFF_AL (OFF_AH + TILE_BYTES)
#define OFF_B0H (OFF_AL + TILE_BYTES)
#define OFF_B0L (OFF_B0H + TILE_BYTES)
#define OFF_B1H (OFF_B0L + TILE_BYTES)
#define OFF_B1L (OFF_B1H + TILE_BYTES)
#define GEMM_SMEM (OFF_B1L + TILE_BYTES)         // 208896, 1 CTA/SM

// ---------------------------------------------------------------------------
// Transpose + split W: Wt[mat][n][k] = W_mat[k][n]
// ---------------------------------------------------------------------------
__global__ __launch_bounds__(256)
void prep_w_kernel(const float* __restrict__ Wq, const float* __restrict__ Wk,
                   const float* __restrict__ Wv) {
    int gid = blockIdx.x * blockDim.x + threadIdx.x;
    if (gid >= 3 * HID * HID) return;
    int mat = gid >> 14;
    int nn  = (gid >> 7) & 127;
    int k   = gid & 127;
    const float* W = (mat == 0) ? Wq : (mat == 1) ? Wk : Wv;
    float x = W[k * HID + nn];
    __nv_bfloat16 hi = __float2bfloat16_rn(x);
    __nv_bfloat16 lo = __float2bfloat16_rn(x - __bfloat162float(hi));
    g_wt_hi[gid] = hi;
    g_wt_lo[gid] = lo;
}

// ---------------------------------------------------------------------------
// GEMM pieces
// ---------------------------------------------------------------------------
__device__ __forceinline__ void load_B_async(int tid, uint32_t sb, int mat,
                                             uint32_t offH, uint32_t offL) {
    const uint4* srcH = reinterpret_cast<const uint4*>(g_wt_hi + (size_t)mat * HID * HID);
    const uint4* srcL = reinterpret_cast<const uint4*>(g_wt_lo + (size_t)mat * HID * HID);
#pragma unroll
    for (int it = 0; it < 8; it++) {
        int t = tid + it * 256;
        int r = t >> 4;
        int c = t & 15;
        uint32_t doff = (uint32_t)(r * (PITCH * 2) + c * 16);
        cp16(sb + offH + doff, srcH + t);
        cp16(sb + offL + doff, srcL + t);
    }
}

// Compute one mat: 8 warps, wm = wid&3 (32 rows), wn = wid>>2 (64 cols).
__device__ __forceinline__ void compute_mat(
    uint32_t sb, uint32_t offBH, uint32_t offBL,
    int row0, int wm, int wn, int lane,
    float* __restrict__ out, const float* __restrict__ bias) {

    const int a_lrow = lane & 15;
    const int a_lsel = lane >> 4;
    const int b_lrow = (lane & 7) + ((lane >> 4) & 1) * 8;
    const int b_lk   = ((lane >> 3) & 1) * 8;

    float acc[2][8][4];
#pragma unroll
    for (int mi = 0; mi < 2; mi++)
#pragma unroll
        for (int ni = 0; ni < 8; ni++)
#pragma unroll
            for (int r = 0; r < 4; r++) acc[mi][ni][r] = 0.f;

#pragma unroll
    for (int ks = 0; ks < 8; ks++) {
        uint32_t aH[2][4], aL[2][4], bH[4][4], bL[4][4];
#pragma unroll
        for (int mi = 0; mi < 2; mi++) {
            uint32_t off = (uint32_t)(((wm * 32 + mi * 16 + a_lrow) * PITCH +
                                       ks * 16 + a_lsel * 8) * 2);
            ldsm_x4(aH[mi], sb + OFF_AH + off);
            ldsm_x4(aL[mi], sb + OFF_AL + off);
        }
#pragma unroll
        for (int np = 0; np < 4; np++) {
            uint32_t off = (uint32_t)(((wn * 64 + np * 16 + b_lrow) * PITCH +
                                       ks * 16 + b_lk) * 2);
            ldsm_x4(bH[np], sb + offBH + off);
            ldsm_x4(bL[np], sb + offBL + off);
        }
#pragma unroll
        for (int mi = 0; mi < 2; mi++)
#pragma unroll
            for (int ni = 0; ni < 8; ni++) {
                int np = ni >> 1, rb = (ni & 1) * 2;
                mma_bf16(acc[mi][ni], aH[mi], bH[np][rb], bH[np][rb + 1]);
                mma_bf16(acc[mi][ni], aH[mi], bL[np][rb], bL[np][rb + 1]);
                mma_bf16(acc[mi][ni], aL[mi], bH[np][rb], bH[np][rb + 1]);
            }
    }

#pragma unroll
    for (int mi = 0; mi < 2; mi++) {
        int row = row0 + wm * 32 + mi * 16 + (lane >> 2);
#pragma unroll
        for (int ni = 0; ni < 8; ni++) {
            int col = wn * 64 + ni * 8 + (lane & 3) * 2;
            float bx = __ldg(&bias[col]);
            float by = __ldg(&bias[col + 1]);
            *reinterpret_cast<float2*>(&out[(size_t)row * HID + col]) =
                make_float2(acc[mi][ni][0] + bx, acc[mi][ni][1] + by);
            *reinterpret_cast<float2*>(&out[(size_t)(row + 8) * HID + col]) =
                make_float2(acc[mi][ni][2] + bx, acc[mi][ni][3] + by);
        }
    }
}

// ---------------------------------------------------------------------------
// Pipelined GEMM: block = 128 rows x 128 cols, K=128 resident.
// B(mat+1) prefetched via cp.async while mat computes.
// ---------------------------------------------------------------------------
__global__ __launch_bounds__(256)
void qkv_gemm_pipe(const float* __restrict__ h,
                   const float* __restrict__ bq, const float* __restrict__ bk,
                   const float* __restrict__ bv, int n) {
    extern __shared__ __align__(16) char smem[];
    const uint32_t sb = smem_u32(smem);
    const int tid  = threadIdx.x;
    const int wid  = tid >> 5;
    const int lane = tid & 31;
    const int wm   = wid & 3;
    const int wn   = wid >> 2;
    const int row0 = blockIdx.x * 128;

    // Kick off B0 prefetch first so it overlaps A staging.
    load_B_async(tid, sb, 0, OFF_B0H, OFF_B0L);
    CP_COMMIT();

    // Stage A: load fp32 h rows, split to bf16 hi/lo, store pitch-136.
    for (int t = tid; t < 4096; t += 256) {
        int r = t >> 5;
        int c = t & 31;                       // float4 index within row
        int row = row0 + r;
        float4 v = make_float4(0.f, 0.f, 0.f, 0.f);
        if (row < n)
            v = *reinterpret_cast<const float4*>(h + (size_t)row * HID + c * 4);
        float hx = __bfloat162float(__float2bfloat16_rn(v.x));
        float hy = __bfloat162float(__float2bfloat16_rn(v.y));
        float hz = __bfloat162float(__float2bfloat16_rn(v.z));
        float hw = __bfloat162float(__float2bfloat16_rn(v.w));
        uint2 phi, plo;
        phi.x = bf2_bits(v.x, v.y);
        phi.y = bf2_bits(v.z, v.w);
        plo.x = bf2_bits(v.x - hx, v.y - hy);
        plo.y = bf2_bits(v.z - hz, v.w - hw);
        uint32_t doff = (uint32_t)(r * (PITCH * 2) + c * 8);
        *reinterpret_cast<uint2*>(smem + OFF_AH + doff) = phi;
        *reinterpret_cast<uint2*>(smem + OFF_AL + doff) = plo;
    }

    // ---- mat 0 ----
    load_B_async(tid, sb, 1, OFF_B1H, OFF_B1L);
    CP_COMMIT();
    CP_WAIT(1);              // B0 landed
    __syncthreads();         // + A staged
    compute_mat(sb, OFF_B0H, OFF_B0L, row0, wm, wn, lane, g_Q, bq);
    __syncthreads();         // everyone done reading B0

    // ---- mat 1 ----
    load_B_async(tid, sb, 2, OFF_B0H, OFF_B0L);
    CP_COMMIT();
    CP_WAIT(1);              // B1 landed
    __syncthreads();
    compute_mat(sb, OFF_B1H, OFF_B1L, row0, wm, wn, lane, g_K, bk);
    __syncthreads();

    // ---- mat 2 ----
    CP_WAIT(0);              // B2 landed
    __syncthreads();
    compute_mat(sb, OFF_B0H, OFF_B0L, row0, wm, wn, lane, g_V, bv);
}

// ---------------------------------------------------------------------------
// CSR construction by destination
// ---------------------------------------------------------------------------
__global__ void zero_kernel(int n) {
    int gid = blockIdx.x * blockDim.x + threadIdx.x;
    if (gid < n) { g_cnt[gid] = 0; g_cursor[gid] = 0; }
}

__global__ void hist_kernel(const int* __restrict__ dst, int e) {
    int gid = blockIdx.x * blockDim.x + threadIdx.x;
    if (gid < e) atomicAdd(&g_cnt[dst[gid]], 1);
}

__global__ void scan_block_kernel(int n) {
    __shared__ int sm[1024];
    int tid = threadIdx.x;
    int gid = blockIdx.x * 1024 + tid;
    int v = (gid < n) ? g_cnt[gid] : 0;
    sm[tid] = v;
    __syncthreads();
    for (int off = 1; off < 1024; off <<= 1) {
        int t = (tid >= off) ? sm[tid - off] : 0;
        __syncthreads();
        sm[tid] += t;
        __syncthreads();
    }
    if (gid < n) g_rowptr[gid] = sm[tid] - v;  // exclusive within block
    if (tid == 1023) g_blksum[blockIdx.x] = sm[1023];
}

__global__ void scan_top_kernel(int nb) {
    if (threadIdx.x == 0) {
        int running = 0;
        for (int i = 0; i < nb; i++) {
            int t = g_blksum[i];
            g_blksum[i] = running;
            running += t;
        }
    }
}

__global__ void add_off_kernel(int n, int e) {
    int gid = blockIdx.x * blockDim.x + threadIdx.x;
    if (gid < n) g_rowptr[gid] += g_blksum[gid >> 10];
    if (gid == 0) g_rowptr[n] = e;
}

__global__ void scatter_kernel(const int* __restrict__ src,
                               const int* __restrict__ dst, int e) {
    int gid = blockIdx.x * blockDim.x + threadIdx.x;
    if (gid < e) {
        int d = dst[gid];
        int pos = g_rowptr[d] + atomicAdd(&g_cursor[d], 1);
        g_ssrc[pos] = src[gid];
    }
}

// ---------------------------------------------------------------------------
// One warp per destination node, online softmax in registers.
// ---------------------------------------------------------------------------
__global__ __launch_bounds__(256)
void attn_kernel(float* __restrict__ out, int n) {
    int gwarp = (blockIdx.x * blockDim.x + threadIdx.x) >> 5;
    if (gwarp >= n) return;
    int lane = threadIdx.x & 31;

    const float4* Q4 = reinterpret_cast<const float4*>(g_Q);
    const float4* K4 = reinterpret_cast<const float4*>(g_K);
    const float4* V4 = reinterpret_cast<const float4*>(g_V);

    float4 q = Q4[(size_t)gwarp * 32 + lane];
    int beg = g_rowptr[gwarp];
    int end = g_rowptr[gwarp + 1];

    float m = -__int_as_float(0x7f800000);  // -inf
    float s = 0.0f;
    float4 acc = make_float4(0.f, 0.f, 0.f, 0.f);

    for (int idx = beg; idx < end; idx++) {
        int sidx = __ldg(&g_ssrc[idx]);
        float4 k = K4[(size_t)sidx * 32 + lane];
        float sc = k.x * q.x + k.y * q.y + k.z * q.z + k.w * q.w;
        sc += __shfl_xor_sync(0xffffffffu, sc, 1);
        sc += __shfl_xor_sync(0xffffffffu, sc, 2);
        float mn = fmaxf(m, sc);
        float scale = __expf(m - mn);   // first iter: exp(-inf) = 0
        float p = __expf(sc - mn);
        float4 v = V4[(size_t)sidx * 32 + lane];
        s = s * scale + p;
        acc.x = acc.x * scale + p * v.x;
        acc.y = acc.y * scale + p * v.y;
        acc.z = acc.z * scale + p * v.z;
        acc.w = acc.w * scale + p * v.w;
        m = mn;
    }

    float4 o;
    if (end > beg) {
        float inv = 1.0f / s;
        o = make_float4(acc.x * inv, acc.y * inv, acc.z * inv, acc.w * inv);
    } else {
        o = make_float4(0.f, 0.f, 0.f, 0.f);
    }
    reinterpret_cast<float4*>(out)[(size_t)gwarp * 32 + lane] = o;
}

// ---------------------------------------------------------------------------
extern "C" void kernel_launch(void* const* d_in, const int* in_sizes, int n_in,
                              void* d_out, int out_size) {
    const float* h   = (const float*)d_in[0];
    const int*   src = (const int*)d_in[1];
    const int*   dst = (const int*)d_in[2];
    const float* Wq  = (const float*)d_in[3];
    const float* bq  = (const float*)d_in[4];
    const float* Wk  = (const float*)d_in[5];
    const float* bk  = (const float*)d_in[6];
    const float* Wv  = (const float*)d_in[7];
    const float* bv  = (const float*)d_in[8];
    float* out = (float*)d_out;

    int n = in_sizes[0] / HID;
    int e = in_sizes[1];

    // One-time infra (created on the uncaptured correctness call).
    static cudaStream_t s2 = nullptr;
    static cudaEvent_t ev_fork = nullptr, ev_join = nullptr;
    if (s2 == nullptr) {
        cudaStreamCreateWithFlags(&s2, cudaStreamNonBlocking);
        cudaEventCreateWithFlags(&ev_fork, cudaEventDisableTiming);
        cudaEventCreateWithFlags(&ev_join, cudaEventDisableTiming);
        cudaFuncSetAttribute(qkv_gemm_pipe,
                             cudaFuncAttributeMaxDynamicSharedMemorySize,
                             GEMM_SMEM);
    }

    // Fork: CSR chain on s2, GEMM chain on the main (capture) stream.
    cudaEventRecord(ev_fork, 0);
    cudaStreamWaitEvent(s2, ev_fork, 0);

    zero_kernel<<<(n + 255) / 256, 256, 0, s2>>>(n);
    hist_kernel<<<(e + 255) / 256, 256, 0, s2>>>(dst, e);
    int nb = (n + 1023) / 1024;
    scan_block_kernel<<<nb, 1024, 0, s2>>>(n);
    scan_top_kernel<<<1, 32, 0, s2>>>(nb);
    add_off_kernel<<<(n + 255) / 256, 256, 0, s2>>>(n, e);
    scatter_kernel<<<(e + 255) / 256, 256, 0, s2>>>(src, dst, e);
    cudaEventRecord(ev_join, s2);

    prep_w_kernel<<<(3 * HID * HID + 255) / 256, 256>>>(Wq, Wk, Wv);
    int mblocks = (n + 127) / 128;
    qkv_gemm_pipe<<<mblocks, 256, GEMM_SMEM>>>(h, bq, bk, bv, n);

    // Join, then attention.
    cudaStreamWaitEvent(0, ev_join, 0);
    long long total_threads = (long long)n * 32;
    int attn_blocks = (int)((total_threads + 255) / 256);
    attn_kernel<<<attn_blocks, 256>>>(out, n);
}